// round 12
// baseline (speedup 1.0000x reference)
#include <cuda_runtime.h>
#include <cuda_bf16.h>
#include <cstring>
#include <cstdint>

#define N_SRC1 500000
#define N_DST1 100000
#define E1     1500000
#define N_DST2 20000
#define E2     200000
#define IN_F   128
#define H_F    256
#define N_CLS  47

#define NB1 98   // ceil(N_DST1/1024)
#define NB2 20   // ceil(N_DST2/1024)
#define NBLK (NB1 + NB2)          // 118 persistent blocks (all co-resident on 148 SMs)
#define NTH  (NBLK * 1024)

// ---------------- scratch (device globals: no allocs allowed) ----------------
__device__ float g_hn1[(size_t)N_DST1 * IN_F];
__device__ float g_h[(size_t)N_DST1 * H_F];
__device__ float g_hn2[(size_t)N_DST2 * H_F];

__device__ __nv_bfloat16 g_Bhi[256 * 256];    // W1 split hi, [n][k]
__device__ __nv_bfloat16 g_Blo[256 * 256];    // W1 split lo, [n][k]
__device__ __nv_bfloat16 g_B2hi[48 * 512];    // W2 split hi, [n][k] (row 47 = 0)
__device__ __nv_bfloat16 g_B2lo[48 * 512];    // W2 split lo, [n][k]

// zero-initialized at module load; re-zeroed by gemm2's tail every replay
__device__ int g_cnt1[N_DST1];
__device__ int g_cnt2[N_DST2];

__device__ int g_row1[N_DST1 + 1];
__device__ int g_cur1[N_DST1];
__device__ int g_eidx1[E1];

__device__ int g_row2[N_DST2 + 1];
__device__ int g_cur2[N_DST2];
__device__ int g_eidx2[E2];

__device__ int g_bsum1[128];
__device__ int g_bsum2[128];
__device__ int g_boff1[128];
__device__ int g_boff2[128];

// grid-barrier counters: monotonic across graph replays; release on count%NBLK==0
__device__ unsigned g_gbar[4];

// ---------------- helpers ----------------
__device__ __forceinline__ uint32_t sptr(const void* p) {
    return (uint32_t)__cvta_generic_to_shared(p);
}

__device__ __forceinline__ void split8(float4 v0, float4 v1, uint4& hi, uint4& lo) {
    float f[8] = {v0.x, v0.y, v0.z, v0.w, v1.x, v1.y, v1.z, v1.w};
    __nv_bfloat16 h[8], l[8];
    #pragma unroll
    for (int i = 0; i < 8; i++) {
        h[i] = __float2bfloat16_rn(f[i]);
        l[i] = __float2bfloat16_rn(f[i] - __bfloat162float(h[i]));
    }
    memcpy(&hi, h, 16);
    memcpy(&lo, l, 16);
}

__device__ __forceinline__ void ldm_x4(uint32_t* r, uint32_t addr) {
    asm volatile("ldmatrix.sync.aligned.m8n8.x4.shared.b16 {%0,%1,%2,%3}, [%4];"
                 : "=r"(r[0]), "=r"(r[1]), "=r"(r[2]), "=r"(r[3]) : "r"(addr));
}
__device__ __forceinline__ void ldm_x2(uint32_t* r, uint32_t addr) {
    asm volatile("ldmatrix.sync.aligned.m8n8.x2.shared.b16 {%0,%1}, [%2];"
                 : "=r"(r[0]), "=r"(r[1]) : "r"(addr));
}
__device__ __forceinline__ void mma16816(float* d, const uint32_t* a, uint32_t b0, uint32_t b1) {
    asm volatile(
        "mma.sync.aligned.m16n8k16.row.col.f32.bf16.bf16.f32 "
        "{%0,%1,%2,%3}, {%4,%5,%6,%7}, {%8,%9}, {%0,%1,%2,%3};"
        : "+f"(d[0]), "+f"(d[1]), "+f"(d[2]), "+f"(d[3])
        : "r"(a[0]), "r"(a[1]), "r"(a[2]), "r"(a[3]), "r"(b0), "r"(b1));
}

// software grid barrier (all NBLK blocks resident). Producer writes are made
// visible via threadfence-before-arrive; consumer acquires via fence after spin.
__device__ __forceinline__ void gbar(int j) {
    __syncthreads();
    if (threadIdx.x == 0) {
        __threadfence();
        atomicAdd(&g_gbar[j], 1u);
        while (atomicAdd(&g_gbar[j], 0u) % (unsigned)NBLK != 0u) { }
        __threadfence();
    }
    __syncthreads();
}

// ---------------- persistent CSR build: split + count | scanA | scanB | scanC | fill ----------------
__global__ __launch_bounds__(1024) void k_build(const int* __restrict__ s1e, const int* __restrict__ d1,
                                                const int* __restrict__ s2e, const int* __restrict__ d2,
                                                const float* __restrict__ Ws1, const float* __restrict__ Wn1,
                                                const float* __restrict__ Ws2, const float* __restrict__ Wn2) {
    __shared__ int s[1024];
    __shared__ int sb1[128];
    __shared__ int sb2[128];
    int t = threadIdx.x;
    int b = blockIdx.x;
    int gid = b * 1024 + t;

    // ---- phase A: weight splits + degree counts ----
    if (gid < 256 * 256) {
        int k = gid >> 8;
        int n = gid & 255;
        float w = (k < 128) ? Ws1[k * 256 + n] : Wn1[(k - 128) * 256 + n];
        __nv_bfloat16 h = __float2bfloat16_rn(w);
        __nv_bfloat16 l = __float2bfloat16_rn(w - __bfloat162float(h));
        g_Bhi[n * 256 + k] = h;
        g_Blo[n * 256 + k] = l;
    }
    if (gid < 48 * 512) {
        int n = gid >> 9;
        int k = gid & 511;
        float w = 0.f;
        if (n < N_CLS) w = (k < 256) ? Ws2[k * N_CLS + n] : Wn2[(k - 256) * N_CLS + n];
        __nv_bfloat16 h = __float2bfloat16_rn(w);
        __nv_bfloat16 l = __float2bfloat16_rn(w - __bfloat162float(h));
        g_B2hi[n * 512 + k] = h;
        g_B2lo[n * 512 + k] = l;
    }
    for (int i = gid; i < E1; i += NTH) atomicAdd(&g_cnt1[d1[i]], 1);
    for (int i = gid; i < E2; i += NTH) atomicAdd(&g_cnt2[d2[i]], 1);
    gbar(0);

    // ---- phase B: per-chunk reduction (scanA) ----
    {
        const int* cnt; int n; int* bsum; int bb;
        if (b < NB1) { cnt = g_cnt1; n = N_DST1; bsum = g_bsum1; bb = b; }
        else         { cnt = g_cnt2; n = N_DST2; bsum = g_bsum2; bb = b - NB1; }
        int i = bb * 1024 + t;
        s[t] = (i < n) ? cnt[i] : 0;
        __syncthreads();
        #pragma unroll
        for (int off = 512; off > 0; off >>= 1) {
            if (t < off) s[t] += s[t + off];
            __syncthreads();
        }
        if (t == 0) bsum[bb] = s[0];
    }
    gbar(1);

    // ---- phase C: block-sum exclusive scan (block 0 only) ----
    if (b == 0) {
        if (t < 128)      sb1[t] = (t < NB1) ? g_bsum1[t] : 0;
        else if (t < 256) { int u = t - 128; sb2[u] = (u < NB2) ? g_bsum2[u] : 0; }
        __syncthreads();
        #pragma unroll
        for (int off = 1; off < 128; off <<= 1) {
            int v = 0;
            if (t < 128)      v = (t >= off) ? sb1[t - off] : 0;
            else if (t < 256) { int u = t - 128; v = (u >= off) ? sb2[u - off] : 0; }
            __syncthreads();
            if (t < 128)      sb1[t] += v;
            else if (t < 256) sb2[t - 128] += v;
            __syncthreads();
        }
        if (t < 128)      { if (t < NB1) g_boff1[t] = (t ? sb1[t - 1] : 0); }
        else if (t < 256) { int u = t - 128; if (u < NB2) g_boff2[u] = (u ? sb2[u - 1] : 0); }
    }
    gbar(2);

    // ---- phase D: per-chunk local exclusive scan + offsets (scanC) ----
    {
        const int* cnt; int n; int* row; int* cur; int boff; int bb; int etot;
        if (b < NB1) { cnt = g_cnt1; n = N_DST1; row = g_row1; cur = g_cur1; bb = b;       boff = g_boff1[bb]; etot = E1; }
        else         { cnt = g_cnt2; n = N_DST2; row = g_row2; cur = g_cur2; bb = b - NB1; boff = g_boff2[bb]; etot = E2; }
        int i = bb * 1024 + t;
        int v = (i < n) ? cnt[i] : 0;
        s[t] = v;
        __syncthreads();
        #pragma unroll
        for (int off = 1; off < 1024; off <<= 1) {
            int u = (t >= off) ? s[t - off] : 0;
            __syncthreads();
            s[t] += u;
            __syncthreads();
        }
        int excl = boff + s[t] - v;
        if (i < n) { row[i] = excl; cur[i] = excl; }
        if (i == n - 1) row[n] = etot;
    }
    gbar(3);

    // ---- phase E: fill edge buckets ----
    for (int i = gid; i < E1; i += NTH) {
        int p = atomicAdd(&g_cur1[d1[i]], 1);
        g_eidx1[p] = s1e[i];
    }
    for (int i = gid; i < E2; i += NTH) {
        int p = atomicAdd(&g_cur2[d2[i]], 1);
        g_eidx2[p] = s2e[i];
    }
}

// tiny spacer so ncu's fixed -s 5 window lands on k_gemm1
__global__ void k_nop() {}

// ---------------- aggregation (warp per dst node) ----------------
__global__ void k_agg1(const float4* __restrict__ x4) {
    int w = (blockIdx.x * blockDim.x + threadIdx.x) >> 5;
    int lane = threadIdx.x & 31;
    if (w >= N_DST1) return;
    int e0 = g_row1[w], e1 = g_row1[w + 1];
    float4 acc = make_float4(0.f, 0.f, 0.f, 0.f);
    int e = e0;
    for (; e + 3 < e1; e += 4) {
        int sa = g_eidx1[e];
        int sb = g_eidx1[e + 1];
        int sc = g_eidx1[e + 2];
        int sd = g_eidx1[e + 3];
        float4 va = __ldg(&x4[(size_t)sa * 32 + lane]);
        float4 vb = __ldg(&x4[(size_t)sb * 32 + lane]);
        float4 vc = __ldg(&x4[(size_t)sc * 32 + lane]);
        float4 vd = __ldg(&x4[(size_t)sd * 32 + lane]);
        acc.x += (va.x + vb.x) + (vc.x + vd.x);
        acc.y += (va.y + vb.y) + (vc.y + vd.y);
        acc.z += (va.z + vb.z) + (vc.z + vd.z);
        acc.w += (va.w + vb.w) + (vc.w + vd.w);
    }
    for (; e < e1; e++) {
        int sa = g_eidx1[e];
        float4 va = __ldg(&x4[(size_t)sa * 32 + lane]);
        acc.x += va.x; acc.y += va.y; acc.z += va.z; acc.w += va.w;
    }
    float inv = 1.0f / fmaxf((float)(e1 - e0), 1.0f);
    acc.x *= inv; acc.y *= inv; acc.z *= inv; acc.w *= inv;
    ((float4*)g_hn1)[(size_t)w * 32 + lane] = acc;
}

__global__ void k_agg2() {
    int w = (blockIdx.x * blockDim.x + threadIdx.x) >> 5;
    int lane = threadIdx.x & 31;
    if (w >= N_DST2) return;
    const float4* h4 = (const float4*)g_h;
    int e0 = g_row2[w], e1 = g_row2[w + 1];
    float4 a0 = make_float4(0.f, 0.f, 0.f, 0.f);
    float4 a1 = make_float4(0.f, 0.f, 0.f, 0.f);
    for (int e = e0; e < e1; e++) {
        int s = g_eidx2[e];
        float4 v0 = __ldg(&h4[(size_t)s * 64 + lane]);
        float4 v1 = __ldg(&h4[(size_t)s * 64 + lane + 32]);
        a0.x += v0.x; a0.y += v0.y; a0.z += v0.z; a0.w += v0.w;
        a1.x += v1.x; a1.y += v1.y; a1.z += v1.z; a1.w += v1.w;
    }
    float inv = 1.0f / fmaxf((float)(e1 - e0), 1.0f);
    a0.x *= inv; a0.y *= inv; a0.z *= inv; a0.w *= inv;
    a1.x *= inv; a1.y *= inv; a1.z *= inv; a1.w *= inv;
    ((float4*)g_hn2)[(size_t)w * 64 + lane] = a0;
    ((float4*)g_hn2)[(size_t)w * 64 + lane + 32] = a1;
}

// ---------------- layer-1 GEMM (HMMA bf16 hi/lo split) — proven 346us version ----------------
#define APITCH 24   // bf16 elements per smem row (16 data + 8 pad = 48B)

__global__ __launch_bounds__(256, 2) void k_gemm1(const float* __restrict__ x,
                                                  const float* __restrict__ b1) {
    __shared__ __nv_bfloat16 sAhi[128 * APITCH];
    __shared__ __nv_bfloat16 sAlo[128 * APITCH];
    __shared__ __nv_bfloat16 sBhi[128 * APITCH];
    __shared__ __nv_bfloat16 sBlo[128 * APITCH];

    int t = threadIdx.x;
    int lane = t & 31;
    int wid = t >> 5;
    int m0 = blockIdx.y * 128;
    int n0 = blockIdx.x * 128;
    int wm = (wid & 3) * 32;
    int wn = (wid >> 2) * 64;

    float acc[2][8][4];
    #pragma unroll
    for (int i = 0; i < 2; i++)
        #pragma unroll
        for (int j = 0; j < 8; j++)
            #pragma unroll
            for (int q = 0; q < 4; q++) acc[i][j][q] = 0.f;

    int lrow = t >> 1;
    int lq   = (t & 1) << 3;
    int grow = m0 + lrow;

    uint32_t aHi = sptr(sAhi), aLo = sptr(sAlo), bHi = sptr(sBhi), bLo = sptr(sBlo);
    int a_r = (lane & 15);
    int a_c = (lane >> 4) << 3;
    int b_r = (lane & 7) + ((lane >> 4) << 3);
    int b_c = ((lane >> 3) & 1) << 3;

    float4 pA0, pA1;
    uint4 pBh, pBl;

    auto ldA = [&](int kc) {
        const float* Ab = (kc < 8) ? (x + kc * 16) : (g_hn1 + (kc - 8) * 16);
        if (grow < N_DST1) {
            const float* p = Ab + (size_t)grow * IN_F + lq;
            pA0 = *(const float4*)p;
            pA1 = *(const float4*)(p + 4);
        } else {
            pA0 = make_float4(0.f, 0.f, 0.f, 0.f);
            pA1 = make_float4(0.f, 0.f, 0.f, 0.f);
        }
    };
    auto ldB = [&](int kc) {
        size_t off = (size_t)(n0 + lrow) * 256 + kc * 16 + lq;
        pBh = *(const uint4*)(g_Bhi + off);
        pBl = *(const uint4*)(g_Blo + off);
    };
    auto sts = [&]() {
        uint4 hi, lo;
        split8(pA0, pA1, hi, lo);
        *(uint4*)&sAhi[lrow * APITCH + lq] = hi;
        *(uint4*)&sAlo[lrow * APITCH + lq] = lo;
        *(uint4*)&sBhi[lrow * APITCH + lq] = pBh;
        *(uint4*)&sBlo[lrow * APITCH + lq] = pBl;
    };
    auto pass = [&](uint32_t abase, uint32_t bbase) {
        uint32_t a[2][4];
        #pragma unroll
        for (int mf = 0; mf < 2; mf++)
            ldm_x4(a[mf], abase + ((wm + mf * 16 + a_r) * APITCH + a_c) * 2);
        #pragma unroll
        for (int pair = 0; pair < 4; pair++) {
            uint32_t bb[4];
            ldm_x4(bb, bbase + ((wn + pair * 16 + b_r) * APITCH + b_c) * 2);
            #pragma unroll
            for (int mf = 0; mf < 2; mf++) {
                mma16816(acc[mf][pair * 2],     a[mf], bb[0], bb[1]);
                mma16816(acc[mf][pair * 2 + 1], a[mf], bb[2], bb[3]);
            }
        }
    };

    ldA(0);
    ldB(0);
    for (int kc = 0; kc < 16; kc++) {
        sts();
        __syncthreads();
        if (kc < 15) { ldA(kc + 1); ldB(kc + 1); }
        pass(aHi, bHi);
        pass(aLo, bHi);
        pass(aHi, bLo);
        __syncthreads();
    }

    #pragma unroll
    for (int mf = 0; mf < 2; mf++) {
        int gr0 = m0 + wm + mf * 16 + (lane >> 2);
        int gr1 = gr0 + 8;
        #pragma unroll
        for (int nf = 0; nf < 8; nf++) {
            int gn = n0 + wn + nf * 8 + ((lane & 3) << 1);
            float bx = b1[gn];
            float by = b1[gn + 1];
            float* d = acc[mf][nf];
            if (gr0 < N_DST1)
                *(float2*)&g_h[(size_t)gr0 * H_F + gn] =
                    make_float2(fmaxf(d[0] + bx, 0.f), fmaxf(d[1] + by, 0.f));
            if (gr1 < N_DST1)
                *(float2*)&g_h[(size_t)gr1 * H_F + gn] =
                    make_float2(fmaxf(d[2] + bx, 0.f), fmaxf(d[3] + by, 0.f));
        }
    }
}

// ---------------- layer-2 GEMM (HMMA bf16 hi/lo) + count-rezero tail ----------------
__global__ __launch_bounds__(256, 2) void k_gemm2(const float* __restrict__ b2,
                                                  float* __restrict__ out) {
    __shared__ __nv_bfloat16 sAhi[128 * APITCH];
    __shared__ __nv_bfloat16 sAlo[128 * APITCH];
    __shared__ __nv_bfloat16 sBhi[48 * APITCH];
    __shared__ __nv_bfloat16 sBlo[48 * APITCH];

    int t = threadIdx.x;
    int lane = t & 31;
    int wid = t >> 5;
    int m0 = blockIdx.x * 128;
    int wm = (wid & 3) * 32;
    int wn = (wid >> 2) * 24;

    float acc[2][3][4];
    #pragma unroll
    for (int i = 0; i < 2; i++)
        #pragma unroll
        for (int j = 0; j < 3; j++)
            #pragma unroll
            for (int q = 0; q < 4; q++) acc[i][j][q] = 0.f;

    int lrow = t >> 1;
    int lq   = (t & 1) << 3;
    int grow = m0 + lrow;

    uint32_t aHi = sptr(sAhi), aLo = sptr(sAlo), bHi = sptr(sBhi), bLo = sptr(sBlo);
    int a_r = (lane & 15);
    int a_c = (lane >> 4) << 3;
    int b_r = (lane & 7) + ((lane >> 4) << 3);
    int b_c = ((lane >> 3) & 1) << 3;
    int b2_r = lane & 7;
    int b2_c = ((lane >> 3) & 1) << 3;

    float4 pA0, pA1;
    uint4 pBq;

    auto ldA = [&](int kc) {
        const float* Ab = (kc < 16) ? (g_h + kc * 16) : (g_hn2 + (kc - 16) * 16);
        if (grow < N_DST2) {
            const float* p = Ab + (size_t)grow * H_F + lq;
            pA0 = *(const float4*)p;
            pA1 = *(const float4*)(p + 4);
        } else {
            pA0 = make_float4(0.f, 0.f, 0.f, 0.f);
            pA1 = make_float4(0.f, 0.f, 0.f, 0.f);
        }
    };
    auto ldB = [&](int kc) {
        if (t < 192) {
            int idx = (t < 96) ? t : (t - 96);
            int row = idx >> 1;
            int half = (idx & 1) << 3;
            const __nv_bfloat16* src = (t < 96) ? g_B2hi : g_B2lo;
            pBq = *(const uint4*)(src + (size_t)row * 512 + kc * 16 + half);
        }
    };
    auto sts = [&]() {
        uint4 hi, lo;
        split8(pA0, pA1, hi, lo);
        *(uint4*)&sAhi[lrow * APITCH + lq] = hi;
        *(uint4*)&sAlo[lrow * APITCH + lq] = lo;
        if (t < 192) {
            int idx = (t < 96) ? t : (t - 96);
            int row = idx >> 1;
            int half = (idx & 1) << 3;
            __nv_bfloat16* dstp = (t < 96) ? sBhi : sBlo;
            *(uint4*)&dstp[row * APITCH + half] = pBq;
        }
    };
    auto pass = [&](uint32_t abase, uint32_t bbase) {
        uint32_t a[2][4];
        #pragma unroll
        for (int mf = 0; mf < 2; mf++)
            ldm_x4(a[mf], abase + ((wm + mf * 16 + a_r) * APITCH + a_c) * 2);
        uint32_t b4[4], bx2[2];
        ldm_x4(b4, bbase + ((wn + b_r) * APITCH + b_c) * 2);
        ldm_x2(bx2, bbase + ((wn + 16 + b2_r) * APITCH + b2_c) * 2);
        #pragma unroll
        for (int mf = 0; mf < 2; mf++) {
            mma16816(acc[mf][0], a[mf], b4[0], b4[1]);
            mma16816(acc[mf][1], a[mf], b4[2], b4[3]);
            mma16816(acc[mf][2], a[mf], bx2[0], bx2[1]);
        }
    };

    ldA(0);
    ldB(0);
    for (int kc = 0; kc < 32; kc++) {
        sts();
        __syncthreads();
        if (kc < 31) { ldA(kc + 1); ldB(kc + 1); }
        pass(aHi, bHi);
        pass(aLo, bHi);
        pass(aHi, bLo);
        __syncthreads();
    }

    #pragma unroll
    for (int mf = 0; mf < 2; mf++) {
        int gr0 = m0 + wm + mf * 16 + (lane >> 2);
        int gr1 = gr0 + 8;
        #pragma unroll
        for (int nf = 0; nf < 3; nf++) {
            int gn = wn + nf * 8 + ((lane & 3) << 1);
            float* d = acc[mf][nf];
            if (gn < N_CLS) {
                float bx = b2[gn];
                if (gr0 < N_DST2) out[(size_t)gr0 * N_CLS + gn] = d[0] + bx;
                if (gr1 < N_DST2) out[(size_t)gr1 * N_CLS + gn] = d[2] + bx;
            }
            if (gn + 1 < N_CLS) {
                float by = b2[gn + 1];
                if (gr0 < N_DST2) out[(size_t)gr0 * N_CLS + gn + 1] = d[1] + by;
                if (gr1 < N_DST2) out[(size_t)gr1 * N_CLS + gn + 1] = d[3] + by;
            }
        }
    }

    // rezero counts for the next graph replay (grid-stride)
    int stride = gridDim.x * blockDim.x;
    for (int i = blockIdx.x * blockDim.x + t; i < N_DST1; i += stride) g_cnt1[i] = 0;
    for (int i = blockIdx.x * blockDim.x + t; i < N_DST2; i += stride) g_cnt2[i] = 0;
}

// ---------------- launch ----------------
extern "C" void kernel_launch(void* const* d_in, const int* in_sizes, int n_in,
                              void* d_out, int out_size) {
    const float* x   = (const float*)d_in[0];
    const float* Ws1 = (const float*)d_in[1];
    const float* Wn1 = (const float*)d_in[2];
    const float* b1  = (const float*)d_in[3];
    const float* Ws2 = (const float*)d_in[4];
    const float* Wn2 = (const float*)d_in[5];
    const float* b2  = (const float*)d_in[6];
    const int* src1  = (const int*)d_in[7];
    const int* dst1  = (const int*)d_in[8];
    const int* src2  = (const int*)d_in[9];
    const int* dst2  = (const int*)d_in[10];
    float* out = (float*)d_out;

    k_build<<<NBLK, 1024>>>(src1, dst1, src2, dst2, Ws1, Wn1, Ws2, Wn2);   // 0
    k_nop<<<1, 32>>>();                                                    // 1 (profiler spacer)
    k_agg1<<<(N_DST1 * 32 + 255) / 256, 256>>>((const float4*)x);          // 2
    dim3 g1(2, (N_DST1 + 127) / 128);
    k_gemm1<<<g1, 256>>>(x, b1);                                           // 3 <- ncu -s 5 target
    k_agg2<<<(N_DST2 * 32 + 255) / 256, 256>>>();                          // 4
    k_gemm2<<<(N_DST2 + 127) / 128, 256>>>(b2, out);                       // 5
}

// round 13
// speedup vs baseline: 1.0401x; 1.0401x over previous
#include <cuda_runtime.h>
#include <cuda_bf16.h>
#include <cstring>
#include <cstdint>

#define N_SRC1 500000
#define N_DST1 100000
#define E1     1500000
#define N_DST2 20000
#define E2     200000
#define IN_F   128
#define H_F    256
#define N_CLS  47

#define NB1 98   // ceil(N_DST1/1024)
#define NB2 20   // ceil(N_DST2/1024)

// ---------------- scratch (device globals: no allocs allowed) ----------------
__device__ float g_hn1[(size_t)N_DST1 * IN_F];
__device__ float g_h[(size_t)N_DST1 * H_F];
__device__ float g_hn2[(size_t)N_DST2 * H_F];

__device__ __nv_bfloat16 g_Bhi[256 * 256];    // W1 split hi, [n][k]
__device__ __nv_bfloat16 g_Blo[256 * 256];    // W1 split lo, [n][k]
__device__ __nv_bfloat16 g_B2hi[48 * 512];    // W2 split hi, [n][k] (row 47 = 0)
__device__ __nv_bfloat16 g_B2lo[48 * 512];    // W2 split lo, [n][k]

// zero-initialized at module load; re-zeroed by gemm2's tail every replay
__device__ int g_cnt1[N_DST1];
__device__ int g_cnt2[N_DST2];

__device__ int g_row1[N_DST1 + 1];
__device__ int g_cur1[N_DST1];
__device__ int g_eidx1[E1];

__device__ int g_row2[N_DST2 + 1];
__device__ int g_cur2[N_DST2];
__device__ int g_eidx2[E2];

__device__ int g_bsum1[128];
__device__ int g_bsum2[128];
__device__ int g_boff1[128];
__device__ int g_boff2[128];

// ---------------- helpers ----------------
__device__ __forceinline__ uint32_t sptr(const void* p) {
    return (uint32_t)__cvta_generic_to_shared(p);
}

__device__ __forceinline__ void split8(float4 v0, float4 v1, uint4& hi, uint4& lo) {
    float f[8] = {v0.x, v0.y, v0.z, v0.w, v1.x, v1.y, v1.z, v1.w};
    __nv_bfloat16 h[8], l[8];
    #pragma unroll
    for (int i = 0; i < 8; i++) {
        h[i] = __float2bfloat16_rn(f[i]);
        l[i] = __float2bfloat16_rn(f[i] - __bfloat162float(h[i]));
    }
    memcpy(&hi, h, 16);
    memcpy(&lo, l, 16);
}

__device__ __forceinline__ void ldm_x4(uint32_t* r, uint32_t addr) {
    asm volatile("ldmatrix.sync.aligned.m8n8.x4.shared.b16 {%0,%1,%2,%3}, [%4];"
                 : "=r"(r[0]), "=r"(r[1]), "=r"(r[2]), "=r"(r[3]) : "r"(addr));
}
__device__ __forceinline__ void ldm_x2(uint32_t* r, uint32_t addr) {
    asm volatile("ldmatrix.sync.aligned.m8n8.x2.shared.b16 {%0,%1}, [%2];"
                 : "=r"(r[0]), "=r"(r[1]) : "r"(addr));
}
__device__ __forceinline__ void mma16816(float* d, const uint32_t* a, uint32_t b0, uint32_t b1) {
    asm volatile(
        "mma.sync.aligned.m16n8k16.row.col.f32.bf16.bf16.f32 "
        "{%0,%1,%2,%3}, {%4,%5,%6,%7}, {%8,%9}, {%0,%1,%2,%3};"
        : "+f"(d[0]), "+f"(d[1]), "+f"(d[2]), "+f"(d[3])
        : "r"(a[0]), "r"(a[1]), "r"(a[2]), "r"(a[3]), "r"(b0), "r"(b1));
}

// ---------------- CSR counts + W1/W2 split (counts pre-zeroed) ----------------
__global__ void k_count_split(const int* __restrict__ d1, const int* __restrict__ d2,
                              const float* __restrict__ Ws1, const float* __restrict__ Wn1,
                              const float* __restrict__ Ws2, const float* __restrict__ Wn2) {
    int i = blockIdx.x * blockDim.x + threadIdx.x;
    if (i < 256 * 256) {   // W1: [k][n] fp32 -> [n][k] bf16 hi/lo
        int k = i >> 8;
        int n = i & 255;
        float w = (k < 128) ? Ws1[k * 256 + n] : Wn1[(k - 128) * 256 + n];
        __nv_bfloat16 h = __float2bfloat16_rn(w);
        __nv_bfloat16 l = __float2bfloat16_rn(w - __bfloat162float(h));
        g_Bhi[n * 256 + k] = h;
        g_Blo[n * 256 + k] = l;
    }
    if (i < 48 * 512) {    // W2: [k][47] fp32 -> [48][512] bf16 hi/lo (row 47 = 0)
        int n = i >> 9;
        int k = i & 511;
        float w = 0.f;
        if (n < N_CLS) w = (k < 256) ? Ws2[k * N_CLS + n] : Wn2[(k - 256) * N_CLS + n];
        __nv_bfloat16 h = __float2bfloat16_rn(w);
        __nv_bfloat16 l = __float2bfloat16_rn(w - __bfloat162float(h));
        g_B2hi[n * 512 + k] = h;
        g_B2lo[n * 512 + k] = l;
    }
    if (i < E1) atomicAdd(&g_cnt1[d1[i]], 1);
    if (i < E2) atomicAdd(&g_cnt2[d2[i]], 1);
}

__global__ void k_scanA() {
    __shared__ int s[1024];
    int b = blockIdx.x;
    const int* cnt; int n; int* bsum; int bb;
    if (b < NB1) { cnt = g_cnt1; n = N_DST1; bsum = g_bsum1; bb = b; }
    else         { cnt = g_cnt2; n = N_DST2; bsum = g_bsum2; bb = b - NB1; }
    int i = bb * 1024 + threadIdx.x;
    int v = (i < n) ? cnt[i] : 0;
    s[threadIdx.x] = v;
    __syncthreads();
    #pragma unroll
    for (int off = 512; off > 0; off >>= 1) {
        if (threadIdx.x < off) s[threadIdx.x] += s[threadIdx.x + off];
        __syncthreads();
    }
    if (threadIdx.x == 0) bsum[bb] = s[0];
}

__global__ void k_scanB() {
    __shared__ int s1[128];
    __shared__ int s2[128];
    int t = threadIdx.x;
    if (t < 128) s1[t] = (t < NB1) ? g_bsum1[t] : 0;
    else         { int u = t - 128; s2[u] = (u < NB2) ? g_bsum2[u] : 0; }
    __syncthreads();
    #pragma unroll
    for (int off = 1; off < 128; off <<= 1) {
        int v;
        if (t < 128) v = (t >= off) ? s1[t - off] : 0;
        else         { int u = t - 128; v = (u >= off) ? s2[u - off] : 0; }
        __syncthreads();
        if (t < 128) s1[t] += v;
        else         s2[t - 128] += v;
        __syncthreads();
    }
    if (t < 128) { if (t < NB1) g_boff1[t] = (t ? s1[t - 1] : 0); }
    else         { int u = t - 128; if (u < NB2) g_boff2[u] = (u ? s2[u - 1] : 0); }
}

__global__ void k_scanC() {
    __shared__ int s[1024];
    int b = blockIdx.x;
    const int* cnt; int n; int* row; int* cur; int boff; int bb; int etot;
    if (b < NB1) { cnt = g_cnt1; n = N_DST1; row = g_row1; cur = g_cur1; bb = b;       boff = g_boff1[bb]; etot = E1; }
    else         { cnt = g_cnt2; n = N_DST2; row = g_row2; cur = g_cur2; bb = b - NB1; boff = g_boff2[bb]; etot = E2; }
    int t = threadIdx.x;
    int i = bb * 1024 + t;
    int v = (i < n) ? cnt[i] : 0;
    s[t] = v;
    __syncthreads();
    #pragma unroll
    for (int off = 1; off < 1024; off <<= 1) {
        int u = (t >= off) ? s[t - off] : 0;
        __syncthreads();
        s[t] += u;
        __syncthreads();
    }
    int excl = boff + s[t] - v;
    if (i < n) { row[i] = excl; cur[i] = excl; }
    if (i == n - 1) row[n] = etot;
}

__global__ void k_fill(const int* __restrict__ s1, const int* __restrict__ d1,
                       const int* __restrict__ s2, const int* __restrict__ d2) {
    int i = blockIdx.x * blockDim.x + threadIdx.x;
    if (i < E1) {
        int p = atomicAdd(&g_cur1[d1[i]], 1);
        g_eidx1[p] = s1[i];
    }
    if (i < E2) {
        int p = atomicAdd(&g_cur2[d2[i]], 1);
        g_eidx2[p] = s2[i];
    }
}

// ---------------- aggregation (warp per dst node) ----------------
__global__ void k_agg1(const float4* __restrict__ x4) {
    int w = (blockIdx.x * blockDim.x + threadIdx.x) >> 5;
    int lane = threadIdx.x & 31;
    if (w >= N_DST1) return;
    int e0 = g_row1[w], e1 = g_row1[w + 1];
    float4 acc = make_float4(0.f, 0.f, 0.f, 0.f);
    int e = e0;
    for (; e + 3 < e1; e += 4) {
        int sa = g_eidx1[e];
        int sb = g_eidx1[e + 1];
        int sc = g_eidx1[e + 2];
        int sd = g_eidx1[e + 3];
        float4 va = __ldg(&x4[(size_t)sa * 32 + lane]);
        float4 vb = __ldg(&x4[(size_t)sb * 32 + lane]);
        float4 vc = __ldg(&x4[(size_t)sc * 32 + lane]);
        float4 vd = __ldg(&x4[(size_t)sd * 32 + lane]);
        acc.x += (va.x + vb.x) + (vc.x + vd.x);
        acc.y += (va.y + vb.y) + (vc.y + vd.y);
        acc.z += (va.z + vb.z) + (vc.z + vd.z);
        acc.w += (va.w + vb.w) + (vc.w + vd.w);
    }
    for (; e < e1; e++) {
        int sa = g_eidx1[e];
        float4 va = __ldg(&x4[(size_t)sa * 32 + lane]);
        acc.x += va.x; acc.y += va.y; acc.z += va.z; acc.w += va.w;
    }
    float inv = 1.0f / fmaxf((float)(e1 - e0), 1.0f);
    acc.x *= inv; acc.y *= inv; acc.z *= inv; acc.w *= inv;
    ((float4*)g_hn1)[(size_t)w * 32 + lane] = acc;
}

__global__ void k_agg2() {
    int w = (blockIdx.x * blockDim.x + threadIdx.x) >> 5;
    int lane = threadIdx.x & 31;
    if (w >= N_DST2) return;
    const float4* h4 = (const float4*)g_h;
    int e0 = g_row2[w], e1 = g_row2[w + 1];
    float4 a0 = make_float4(0.f, 0.f, 0.f, 0.f);
    float4 a1 = make_float4(0.f, 0.f, 0.f, 0.f);
    for (int e = e0; e < e1; e++) {
        int s = g_eidx2[e];
        float4 v0 = __ldg(&h4[(size_t)s * 64 + lane]);
        float4 v1 = __ldg(&h4[(size_t)s * 64 + lane + 32]);
        a0.x += v0.x; a0.y += v0.y; a0.z += v0.z; a0.w += v0.w;
        a1.x += v1.x; a1.y += v1.y; a1.z += v1.z; a1.w += v1.w;
    }
    float inv = 1.0f / fmaxf((float)(e1 - e0), 1.0f);
    a0.x *= inv; a0.y *= inv; a0.z *= inv; a0.w *= inv;
    a1.x *= inv; a1.y *= inv; a1.z *= inv; a1.w *= inv;
    ((float4*)g_hn2)[(size_t)w * 64 + lane] = a0;
    ((float4*)g_hn2)[(size_t)w * 64 + lane + 32] = a1;
}

// ---------------- layer-1 GEMM (HMMA bf16 hi/lo, fragment-reuse inner loop) ----------------
// Per k-chunk: 12 ldmatrix (was 18) — aHi/aLo loaded once, bHi/bLo once per pair,
// all three products (ah*bh, al*bh, ah*bl) issued from registers.
#define APITCH 24   // bf16 elements per smem row (16 data + 8 pad = 48B)

__global__ __launch_bounds__(256, 2) void k_gemm1(const float* __restrict__ x,
                                                  const float* __restrict__ b1) {
    __shared__ __nv_bfloat16 sAhi[128 * APITCH];
    __shared__ __nv_bfloat16 sAlo[128 * APITCH];
    __shared__ __nv_bfloat16 sBhi[128 * APITCH];
    __shared__ __nv_bfloat16 sBlo[128 * APITCH];

    int t = threadIdx.x;
    int lane = t & 31;
    int wid = t >> 5;
    int m0 = blockIdx.y * 128;
    int n0 = blockIdx.x * 128;
    int wm = (wid & 3) * 32;
    int wn = (wid >> 2) * 64;

    float acc[2][8][4];
    #pragma unroll
    for (int i = 0; i < 2; i++)
        #pragma unroll
        for (int j = 0; j < 8; j++)
            #pragma unroll
            for (int q = 0; q < 4; q++) acc[i][j][q] = 0.f;

    int lrow = t >> 1;
    int lq   = (t & 1) << 3;
    int grow = m0 + lrow;

    uint32_t aHi = sptr(sAhi), aLo = sptr(sAlo), bHi = sptr(sBhi), bLo = sptr(sBlo);
    int a_r = (lane & 15);
    int a_c = (lane >> 4) << 3;
    int b_r = (lane & 7) + ((lane >> 4) << 3);
    int b_c = ((lane >> 3) & 1) << 3;

    float4 pA0, pA1;
    uint4 pBh, pBl;

    auto ldA = [&](int kc) {
        const float* Ab = (kc < 8) ? (x + kc * 16) : (g_hn1 + (kc - 8) * 16);
        if (grow < N_DST1) {
            const float* p = Ab + (size_t)grow * IN_F + lq;
            pA0 = *(const float4*)p;
            pA1 = *(const float4*)(p + 4);
        } else {
            pA0 = make_float4(0.f, 0.f, 0.f, 0.f);
            pA1 = make_float4(0.f, 0.f, 0.f, 0.f);
        }
    };
    auto ldB = [&](int kc) {
        size_t off = (size_t)(n0 + lrow) * 256 + kc * 16 + lq;
        pBh = *(const uint4*)(g_Bhi + off);
        pBl = *(const uint4*)(g_Blo + off);
    };
    auto sts = [&]() {
        uint4 hi, lo;
        split8(pA0, pA1, hi, lo);
        *(uint4*)&sAhi[lrow * APITCH + lq] = hi;
        *(uint4*)&sAlo[lrow * APITCH + lq] = lo;
        *(uint4*)&sBhi[lrow * APITCH + lq] = pBh;
        *(uint4*)&sBlo[lrow * APITCH + lq] = pBl;
    };
    auto fused = [&]() {
        uint32_t ah[2][4], al[2][4];
        #pragma unroll
        for (int mf = 0; mf < 2; mf++) {
            uint32_t ao = ((wm + mf * 16 + a_r) * APITCH + a_c) * 2;
            ldm_x4(ah[mf], aHi + ao);
            ldm_x4(al[mf], aLo + ao);
        }
        #pragma unroll
        for (int pair = 0; pair < 4; pair++) {
            uint32_t bo = ((wn + pair * 16 + b_r) * APITCH + b_c) * 2;
            uint32_t bh[4], bl[4];
            ldm_x4(bh, bHi + bo);
            ldm_x4(bl, bLo + bo);
            #pragma unroll
            for (int mf = 0; mf < 2; mf++) {
                float* d0 = acc[mf][pair * 2];
                float* d1 = acc[mf][pair * 2 + 1];
                mma16816(d0, ah[mf], bh[0], bh[1]);
                mma16816(d1, ah[mf], bh[2], bh[3]);
                mma16816(d0, al[mf], bh[0], bh[1]);
                mma16816(d1, al[mf], bh[2], bh[3]);
                mma16816(d0, ah[mf], bl[0], bl[1]);
                mma16816(d1, ah[mf], bl[2], bl[3]);
            }
        }
    };

    ldA(0);
    ldB(0);
    for (int kc = 0; kc < 16; kc++) {
        sts();
        __syncthreads();
        if (kc < 15) { ldA(kc + 1); ldB(kc + 1); }
        fused();
        __syncthreads();
    }

    #pragma unroll
    for (int mf = 0; mf < 2; mf++) {
        int gr0 = m0 + wm + mf * 16 + (lane >> 2);
        int gr1 = gr0 + 8;
        #pragma unroll
        for (int nf = 0; nf < 8; nf++) {
            int gn = n0 + wn + nf * 8 + ((lane & 3) << 1);
            float bx = b1[gn];
            float by = b1[gn + 1];
            float* d = acc[mf][nf];
            if (gr0 < N_DST1)
                *(float2*)&g_h[(size_t)gr0 * H_F + gn] =
                    make_float2(fmaxf(d[0] + bx, 0.f), fmaxf(d[1] + by, 0.f));
            if (gr1 < N_DST1)
                *(float2*)&g_h[(size_t)gr1 * H_F + gn] =
                    make_float2(fmaxf(d[2] + bx, 0.f), fmaxf(d[3] + by, 0.f));
        }
    }
}

// ---------------- layer-2 GEMM (HMMA bf16 hi/lo, fragment-reuse) + rezero tail ----------------
__global__ __launch_bounds__(256, 2) void k_gemm2(const float* __restrict__ b2,
                                                  float* __restrict__ out) {
    __shared__ __nv_bfloat16 sAhi[128 * APITCH];
    __shared__ __nv_bfloat16 sAlo[128 * APITCH];
    __shared__ __nv_bfloat16 sBhi[48 * APITCH];
    __shared__ __nv_bfloat16 sBlo[48 * APITCH];

    int t = threadIdx.x;
    int lane = t & 31;
    int wid = t >> 5;
    int m0 = blockIdx.x * 128;
    int wm = (wid & 3) * 32;
    int wn = (wid >> 2) * 24;

    float acc[2][3][4];
    #pragma unroll
    for (int i = 0; i < 2; i++)
        #pragma unroll
        for (int j = 0; j < 3; j++)
            #pragma unroll
            for (int q = 0; q < 4; q++) acc[i][j][q] = 0.f;

    int lrow = t >> 1;
    int lq   = (t & 1) << 3;
    int grow = m0 + lrow;

    uint32_t aHi = sptr(sAhi), aLo = sptr(sAlo), bHi = sptr(sBhi), bLo = sptr(sBlo);
    int a_r = (lane & 15);
    int a_c = (lane >> 4) << 3;
    int b_r = (lane & 7) + ((lane >> 4) << 3);
    int b_c = ((lane >> 3) & 1) << 3;
    int b2_r = lane & 7;
    int b2_c = ((lane >> 3) & 1) << 3;

    float4 pA0, pA1;
    uint4 pBq;

    auto ldA = [&](int kc) {
        const float* Ab = (kc < 16) ? (g_h + kc * 16) : (g_hn2 + (kc - 16) * 16);
        if (grow < N_DST2) {
            const float* p = Ab + (size_t)grow * H_F + lq;
            pA0 = *(const float4*)p;
            pA1 = *(const float4*)(p + 4);
        } else {
            pA0 = make_float4(0.f, 0.f, 0.f, 0.f);
            pA1 = make_float4(0.f, 0.f, 0.f, 0.f);
        }
    };
    auto ldB = [&](int kc) {
        if (t < 192) {
            int idx = (t < 96) ? t : (t - 96);
            int row = idx >> 1;
            int half = (idx & 1) << 3;
            const __nv_bfloat16* src = (t < 96) ? g_B2hi : g_B2lo;
            pBq = *(const uint4*)(src + (size_t)row * 512 + kc * 16 + half);
        }
    };
    auto sts = [&]() {
        uint4 hi, lo;
        split8(pA0, pA1, hi, lo);
        *(uint4*)&sAhi[lrow * APITCH + lq] = hi;
        *(uint4*)&sAlo[lrow * APITCH + lq] = lo;
        if (t < 192) {
            int idx = (t < 96) ? t : (t - 96);
            int row = idx >> 1;
            int half = (idx & 1) << 3;
            __nv_bfloat16* dstp = (t < 96) ? sBhi : sBlo;
            *(uint4*)&dstp[row * APITCH + half] = pBq;
        }
    };
    auto fused = [&]() {
        uint32_t ah[2][4], al[2][4];
        #pragma unroll
        for (int mf = 0; mf < 2; mf++) {
            uint32_t ao = ((wm + mf * 16 + a_r) * APITCH + a_c) * 2;
            ldm_x4(ah[mf], aHi + ao);
            ldm_x4(al[mf], aLo + ao);
        }
        uint32_t bh4[4], bh2[2], bl4[4], bl2[2];
        uint32_t bo4 = ((wn + b_r) * APITCH + b_c) * 2;
        uint32_t bo2 = ((wn + 16 + b2_r) * APITCH + b2_c) * 2;
        ldm_x4(bh4, bHi + bo4);
        ldm_x2(bh2, bHi + bo2);
        ldm_x4(bl4, bLo + bo4);
        ldm_x2(bl2, bLo + bo2);
        #pragma unroll
        for (int mf = 0; mf < 2; mf++) {
            mma16816(acc[mf][0], ah[mf], bh4[0], bh4[1]);
            mma16816(acc[mf][1], ah[mf], bh4[2], bh4[3]);
            mma16816(acc[mf][2], ah[mf], bh2[0], bh2[1]);
            mma16816(acc[mf][0], al[mf], bh4[0], bh4[1]);
            mma16816(acc[mf][1], al[mf], bh4[2], bh4[3]);
            mma16816(acc[mf][2], al[mf], bh2[0], bh2[1]);
            mma16816(acc[mf][0], ah[mf], bl4[0], bl4[1]);
            mma16816(acc[mf][1], ah[mf], bl4[2], bl4[3]);
            mma16816(acc[mf][2], ah[mf], bl2[0], bl2[1]);
        }
    };

    ldA(0);
    ldB(0);
    for (int kc = 0; kc < 32; kc++) {
        sts();
        __syncthreads();
        if (kc < 31) { ldA(kc + 1); ldB(kc + 1); }
        fused();
        __syncthreads();
    }

    #pragma unroll
    for (int mf = 0; mf < 2; mf++) {
        int gr0 = m0 + wm + mf * 16 + (lane >> 2);
        int gr1 = gr0 + 8;
        #pragma unroll
        for (int nf = 0; nf < 3; nf++) {
            int gn = wn + nf * 8 + ((lane & 3) << 1);
            float* d = acc[mf][nf];
            if (gn < N_CLS) {
                float bx = b2[gn];
                if (gr0 < N_DST2) out[(size_t)gr0 * N_CLS + gn] = d[0] + bx;
                if (gr1 < N_DST2) out[(size_t)gr1 * N_CLS + gn] = d[2] + bx;
            }
            if (gn + 1 < N_CLS) {
                float by = b2[gn + 1];
                if (gr0 < N_DST2) out[(size_t)gr0 * N_CLS + gn + 1] = d[1] + by;
                if (gr1 < N_DST2) out[(size_t)gr1 * N_CLS + gn + 1] = d[3] + by;
            }
        }
    }

    // rezero counts for the next graph replay (grid-stride)
    int stride = gridDim.x * blockDim.x;
    for (int i = blockIdx.x * blockDim.x + t; i < N_DST1; i += stride) g_cnt1[i] = 0;
    for (int i = blockIdx.x * blockDim.x + t; i < N_DST2; i += stride) g_cnt2[i] = 0;
}

// ---------------- launch ----------------
extern "C" void kernel_launch(void* const* d_in, const int* in_sizes, int n_in,
                              void* d_out, int out_size) {
    const float* x   = (const float*)d_in[0];
    const float* Ws1 = (const float*)d_in[1];
    const float* Wn1 = (const float*)d_in[2];
    const float* b1  = (const float*)d_in[3];
    const float* Ws2 = (const float*)d_in[4];
    const float* Wn2 = (const float*)d_in[5];
    const float* b2  = (const float*)d_in[6];
    const int* src1  = (const int*)d_in[7];
    const int* dst1  = (const int*)d_in[8];
    const int* src2  = (const int*)d_in[9];
    const int* dst2  = (const int*)d_in[10];
    float* out = (float*)d_out;

    k_count_split<<<(E1 + 255) / 256, 256>>>(dst1, dst2, Ws1, Wn1, Ws2, Wn2);  // 0
    k_scanA<<<NB1 + NB2, 1024>>>();                                            // 1
    k_scanB<<<1, 256>>>();                                                     // 2
    k_scanC<<<NB1 + NB2, 1024>>>();                                            // 3
    k_fill<<<(E1 + 255) / 256, 256>>>(src1, dst1, src2, dst2);                 // 4
    k_agg1<<<(N_DST1 * 32 + 255) / 256, 256>>>((const float4*)x);              // 5
    dim3 g1(2, (N_DST1 + 127) / 128);
    k_gemm1<<<g1, 256>>>(x, b1);                                               // 6
    k_agg2<<<(N_DST2 * 32 + 255) / 256, 256>>>();                              // 7
    k_gemm2<<<(N_DST2 + 127) / 128, 256>>>(b2, out);                           // 8
}

// round 14
// speedup vs baseline: 1.1941x; 1.1481x over previous
#include <cuda_runtime.h>
#include <cuda_fp16.h>
#include <cstring>
#include <cstdint>

#define N_SRC1 500000
#define N_DST1 100000
#define E1     1500000
#define N_DST2 20000
#define E2     200000
#define IN_F   128
#define H_F    256
#define N_CLS  47

#define NB1 98   // ceil(N_DST1/1024)
#define NB2 20   // ceil(N_DST2/1024)

// ---------------- scratch (device globals: no allocs allowed) ----------------
__device__ float g_hn1[(size_t)N_DST1 * IN_F];
__device__ float g_h[(size_t)N_DST1 * H_F];
__device__ float g_hn2[(size_t)N_DST2 * H_F];

__device__ __half g_W1[256 * 256];    // W1 fp16, [n][k]
__device__ __half g_W2[48 * 512];     // W2 fp16, [n][k] (row 47 = 0)

// zero-initialized at module load; re-zeroed by gemm2's tail every replay
__device__ int g_cnt1[N_DST1];
__device__ int g_cnt2[N_DST2];

__device__ int g_row1[N_DST1 + 1];
__device__ int g_cur1[N_DST1];
__device__ int g_eidx1[E1];

__device__ int g_row2[N_DST2 + 1];
__device__ int g_cur2[N_DST2];
__device__ int g_eidx2[E2];

__device__ int g_bsum1[128];
__device__ int g_bsum2[128];

// ---------------- helpers ----------------
__device__ __forceinline__ uint32_t sptr(const void* p) {
    return (uint32_t)__cvta_generic_to_shared(p);
}

// split 8 fp32 into fp16 hi/lo packs (A operand: ~22-bit accuracy)
__device__ __forceinline__ void split8h(float4 v0, float4 v1, uint4& hi, uint4& lo) {
    float f[8] = {v0.x, v0.y, v0.z, v0.w, v1.x, v1.y, v1.z, v1.w};
    __half h[8], l[8];
    #pragma unroll
    for (int i = 0; i < 8; i++) {
        h[i] = __float2half_rn(f[i]);
        l[i] = __float2half_rn(f[i] - __half2float(h[i]));
    }
    memcpy(&hi, h, 16);
    memcpy(&lo, l, 16);
}

__device__ __forceinline__ void ldm_x4(uint32_t* r, uint32_t addr) {
    asm volatile("ldmatrix.sync.aligned.m8n8.x4.shared.b16 {%0,%1,%2,%3}, [%4];"
                 : "=r"(r[0]), "=r"(r[1]), "=r"(r[2]), "=r"(r[3]) : "r"(addr));
}
__device__ __forceinline__ void ldm_x2(uint32_t* r, uint32_t addr) {
    asm volatile("ldmatrix.sync.aligned.m8n8.x2.shared.b16 {%0,%1}, [%2];"
                 : "=r"(r[0]), "=r"(r[1]) : "r"(addr));
}
__device__ __forceinline__ void mma16816(float* d, const uint32_t* a, uint32_t b0, uint32_t b1) {
    asm volatile(
        "mma.sync.aligned.m16n8k16.row.col.f32.f16.f16.f32 "
        "{%0,%1,%2,%3}, {%4,%5,%6,%7}, {%8,%9}, {%0,%1,%2,%3};"
        : "+f"(d[0]), "+f"(d[1]), "+f"(d[2]), "+f"(d[3])
        : "r"(a[0]), "r"(a[1]), "r"(a[2]), "r"(a[3]), "r"(b0), "r"(b1));
}

// ---------------- CSR counts + W1/W2 fp16 transpose (counts pre-zeroed) ----------------
__global__ void k_count_split(const int* __restrict__ d1, const int* __restrict__ d2,
                              const float* __restrict__ Ws1, const float* __restrict__ Wn1,
                              const float* __restrict__ Ws2, const float* __restrict__ Wn2) {
    int i = blockIdx.x * blockDim.x + threadIdx.x;
    if (i < 256 * 256) {   // W1: [k][n] fp32 -> [n][k] fp16
        int k = i >> 8;
        int n = i & 255;
        float w = (k < 128) ? Ws1[k * 256 + n] : Wn1[(k - 128) * 256 + n];
        g_W1[n * 256 + k] = __float2half_rn(w);
    }
    if (i < 48 * 512) {    // W2: [k][47] fp32 -> [48][512] fp16 (row 47 = 0)
        int n = i >> 9;
        int k = i & 511;
        float w = 0.f;
        if (n < N_CLS) w = (k < 256) ? Ws2[k * N_CLS + n] : Wn2[(k - 256) * N_CLS + n];
        g_W2[n * 512 + k] = __float2half_rn(w);
    }
    if (i < E1) atomicAdd(&g_cnt1[d1[i]], 1);
    if (i < E2) atomicAdd(&g_cnt2[d2[i]], 1);
}

__global__ void k_scanA() {
    __shared__ int s[1024];
    int b = blockIdx.x;
    const int* cnt; int n; int* bsum; int bb;
    if (b < NB1) { cnt = g_cnt1; n = N_DST1; bsum = g_bsum1; bb = b; }
    else         { cnt = g_cnt2; n = N_DST2; bsum = g_bsum2; bb = b - NB1; }
    int i = bb * 1024 + threadIdx.x;
    int v = (i < n) ? cnt[i] : 0;
    s[threadIdx.x] = v;
    __syncthreads();
    #pragma unroll
    for (int off = 512; off > 0; off >>= 1) {
        if (threadIdx.x < off) s[threadIdx.x] += s[threadIdx.x + off];
        __syncthreads();
    }
    if (threadIdx.x == 0) bsum[bb] = s[0];
}

// scanC with scanB folded in: each block re-scans the (<=128) block sums locally.
__global__ void k_scanC() {
    __shared__ int s[1024];
    __shared__ int sbs[128];
    int b = blockIdx.x;
    const int* cnt; int n; int* row; int* cur; int bb; int etot; const int* bsum; int nb;
    if (b < NB1) { cnt = g_cnt1; n = N_DST1; row = g_row1; cur = g_cur1; bb = b;       etot = E1; bsum = g_bsum1; nb = NB1; }
    else         { cnt = g_cnt2; n = N_DST2; row = g_row2; cur = g_cur2; bb = b - NB1; etot = E2; bsum = g_bsum2; nb = NB2; }
    int t = threadIdx.x;

    if (t < 128) sbs[t] = (t < nb) ? bsum[t] : 0;
    __syncthreads();
    #pragma unroll
    for (int off = 1; off < 128; off <<= 1) {
        int v = 0;
        if (t < 128 && t >= off) v = sbs[t - off];
        __syncthreads();
        if (t < 128) sbs[t] += v;
        __syncthreads();
    }
    int boff = (bb > 0) ? sbs[bb - 1] : 0;

    int i = bb * 1024 + t;
    int v = (i < n) ? cnt[i] : 0;
    s[t] = v;
    __syncthreads();
    #pragma unroll
    for (int off = 1; off < 1024; off <<= 1) {
        int u = (t >= off) ? s[t - off] : 0;
        __syncthreads();
        s[t] += u;
        __syncthreads();
    }
    int excl = boff + s[t] - v;
    if (i < n) { row[i] = excl; cur[i] = excl; }
    if (i == n - 1) row[n] = etot;
}

__global__ void k_fill(const int* __restrict__ s1, const int* __restrict__ d1,
                       const int* __restrict__ s2, const int* __restrict__ d2) {
    int i = blockIdx.x * blockDim.x + threadIdx.x;
    if (i < E1) {
        int p = atomicAdd(&g_cur1[d1[i]], 1);
        g_eidx1[p] = s1[i];
    }
    if (i < E2) {
        int p = atomicAdd(&g_cur2[d2[i]], 1);
        g_eidx2[p] = s2[i];
    }
}

// ---------------- aggregation (warp per dst node, deep unroll for MLP) ----------------
__global__ void k_agg1(const float4* __restrict__ x4) {
    int w = (blockIdx.x * blockDim.x + threadIdx.x) >> 5;
    int lane = threadIdx.x & 31;
    if (w >= N_DST1) return;
    int e0 = g_row1[w], e1 = g_row1[w + 1];
    float4 acc = make_float4(0.f, 0.f, 0.f, 0.f);
    int e = e0;
    for (; e + 7 < e1; e += 8) {
        int si[8];
        #pragma unroll
        for (int j = 0; j < 8; j++) si[j] = g_eidx1[e + j];
        float4 v[8];
        #pragma unroll
        for (int j = 0; j < 8; j++) v[j] = __ldg(&x4[(size_t)si[j] * 32 + lane]);
        #pragma unroll
        for (int j = 0; j < 8; j++) {
            acc.x += v[j].x; acc.y += v[j].y; acc.z += v[j].z; acc.w += v[j].w;
        }
    }
    for (; e + 3 < e1; e += 4) {
        int si[4];
        #pragma unroll
        for (int j = 0; j < 4; j++) si[j] = g_eidx1[e + j];
        float4 v[4];
        #pragma unroll
        for (int j = 0; j < 4; j++) v[j] = __ldg(&x4[(size_t)si[j] * 32 + lane]);
        #pragma unroll
        for (int j = 0; j < 4; j++) {
            acc.x += v[j].x; acc.y += v[j].y; acc.z += v[j].z; acc.w += v[j].w;
        }
    }
    for (; e < e1; e++) {
        int sa = g_eidx1[e];
        float4 va = __ldg(&x4[(size_t)sa * 32 + lane]);
        acc.x += va.x; acc.y += va.y; acc.z += va.z; acc.w += va.w;
    }
    float inv = 1.0f / fmaxf((float)(e1 - e0), 1.0f);
    acc.x *= inv; acc.y *= inv; acc.z *= inv; acc.w *= inv;
    ((float4*)g_hn1)[(size_t)w * 32 + lane] = acc;
}

__global__ void k_agg2() {
    int w = (blockIdx.x * blockDim.x + threadIdx.x) >> 5;
    int lane = threadIdx.x & 31;
    if (w >= N_DST2) return;
    const float4* h4 = (const float4*)g_h;
    int e0 = g_row2[w], e1 = g_row2[w + 1];
    float4 a0 = make_float4(0.f, 0.f, 0.f, 0.f);
    float4 a1 = make_float4(0.f, 0.f, 0.f, 0.f);
    int e = e0;
    for (; e + 1 < e1; e += 2) {
        int sa = g_eidx2[e];
        int sb = g_eidx2[e + 1];
        float4 va0 = __ldg(&h4[(size_t)sa * 64 + lane]);
        float4 va1 = __ldg(&h4[(size_t)sa * 64 + lane + 32]);
        float4 vb0 = __ldg(&h4[(size_t)sb * 64 + lane]);
        float4 vb1 = __ldg(&h4[(size_t)sb * 64 + lane + 32]);
        a0.x += va0.x + vb0.x; a0.y += va0.y + vb0.y;
        a0.z += va0.z + vb0.z; a0.w += va0.w + vb0.w;
        a1.x += va1.x + vb1.x; a1.y += va1.y + vb1.y;
        a1.z += va1.z + vb1.z; a1.w += va1.w + vb1.w;
    }
    for (; e < e1; e++) {
        int s = g_eidx2[e];
        float4 v0 = __ldg(&h4[(size_t)s * 64 + lane]);
        float4 v1 = __ldg(&h4[(size_t)s * 64 + lane + 32]);
        a0.x += v0.x; a0.y += v0.y; a0.z += v0.z; a0.w += v0.w;
        a1.x += v1.x; a1.y += v1.y; a1.z += v1.z; a1.w += v1.w;
    }
    float inv = 1.0f / fmaxf((float)(e1 - e0), 1.0f);
    a0.x *= inv; a0.y *= inv; a0.z *= inv; a0.w *= inv;
    a1.x *= inv; a1.y *= inv; a1.z *= inv; a1.w *= inv;
    ((float4*)g_hn2)[(size_t)w * 64 + lane] = a0;
    ((float4*)g_hn2)[(size_t)w * 64 + lane + 32] = a1;
}

// ---------------- layer-1 GEMM (HMMA fp16: A hi/lo 2-pass, B fp16) ----------------
#define APITCH 24   // fp16 elements per smem row (16 data + 8 pad = 48B)

__global__ __launch_bounds__(256, 2) void k_gemm1(const float* __restrict__ x,
                                                  const float* __restrict__ b1) {
    __shared__ __half sAhi[128 * APITCH];
    __shared__ __half sAlo[128 * APITCH];
    __shared__ __half sB[128 * APITCH];

    int t = threadIdx.x;
    int lane = t & 31;
    int wid = t >> 5;
    int m0 = blockIdx.y * 128;
    int n0 = blockIdx.x * 128;
    int wm = (wid & 3) * 32;
    int wn = (wid >> 2) * 64;

    float acc[2][8][4];
    #pragma unroll
    for (int i = 0; i < 2; i++)
        #pragma unroll
        for (int j = 0; j < 8; j++)
            #pragma unroll
            for (int q = 0; q < 4; q++) acc[i][j][q] = 0.f;

    int lrow = t >> 1;
    int lq   = (t & 1) << 3;
    int grow = m0 + lrow;

    uint32_t aHi = sptr(sAhi), aLo = sptr(sAlo), bB = sptr(sB);
    int a_r = (lane & 15);
    int a_c = (lane >> 4) << 3;
    int b_r = (lane & 7) + ((lane >> 4) << 3);
    int b_c = ((lane >> 3) & 1) << 3;

    float4 pA0, pA1;
    uint4 pB;

    auto ldA = [&](int kc) {
        const float* Ab = (kc < 8) ? (x + kc * 16) : (g_hn1 + (kc - 8) * 16);
        if (grow < N_DST1) {
            const float* p = Ab + (size_t)grow * IN_F + lq;
            pA0 = *(const float4*)p;
            pA1 = *(const float4*)(p + 4);
        } else {
            pA0 = make_float4(0.f, 0.f, 0.f, 0.f);
            pA1 = make_float4(0.f, 0.f, 0.f, 0.f);
        }
    };
    auto ldB = [&](int kc) {
        pB = *(const uint4*)(g_W1 + (size_t)(n0 + lrow) * 256 + kc * 16 + lq);
    };
    auto sts = [&]() {
        uint4 hi, lo;
        split8h(pA0, pA1, hi, lo);
        *(uint4*)&sAhi[lrow * APITCH + lq] = hi;
        *(uint4*)&sAlo[lrow * APITCH + lq] = lo;
        *(uint4*)&sB[lrow * APITCH + lq] = pB;
    };
    auto fused = [&]() {
        uint32_t ah[2][4], al[2][4];
        #pragma unroll
        for (int mf = 0; mf < 2; mf++) {
            uint32_t ao = ((wm + mf * 16 + a_r) * APITCH + a_c) * 2;
            ldm_x4(ah[mf], aHi + ao);
            ldm_x4(al[mf], aLo + ao);
        }
        #pragma unroll
        for (int pair = 0; pair < 4; pair++) {
            uint32_t bb[4];
            ldm_x4(bb, bB + ((wn + pair * 16 + b_r) * APITCH + b_c) * 2);
            #pragma unroll
            for (int mf = 0; mf < 2; mf++) {
                float* d0 = acc[mf][pair * 2];
                float* d1 = acc[mf][pair * 2 + 1];
                mma16816(d0, ah[mf], bb[0], bb[1]);
                mma16816(d1, ah[mf], bb[2], bb[3]);
                mma16816(d0, al[mf], bb[0], bb[1]);
                mma16816(d1, al[mf], bb[2], bb[3]);
            }
        }
    };

    ldA(0);
    ldB(0);
    for (int kc = 0; kc < 16; kc++) {
        sts();
        __syncthreads();
        if (kc < 15) { ldA(kc + 1); ldB(kc + 1); }
        fused();
        __syncthreads();
    }

    #pragma unroll
    for (int mf = 0; mf < 2; mf++) {
        int gr0 = m0 + wm + mf * 16 + (lane >> 2);
        int gr1 = gr0 + 8;
        #pragma unroll
        for (int nf = 0; nf < 8; nf++) {
            int gn = n0 + wn + nf * 8 + ((lane & 3) << 1);
            float bx = b1[gn];
            float by = b1[gn + 1];
            float* d = acc[mf][nf];
            if (gr0 < N_DST1)
                *(float2*)&g_h[(size_t)gr0 * H_F + gn] =
                    make_float2(fmaxf(d[0] + bx, 0.f), fmaxf(d[1] + by, 0.f));
            if (gr1 < N_DST1)
                *(float2*)&g_h[(size_t)gr1 * H_F + gn] =
                    make_float2(fmaxf(d[2] + bx, 0.f), fmaxf(d[3] + by, 0.f));
        }
    }
}

// ---------------- layer-2 GEMM (HMMA fp16 2-pass) + count-rezero tail ----------------
__global__ __launch_bounds__(256, 2) void k_gemm2(const float* __restrict__ b2,
                                                  float* __restrict__ out) {
    __shared__ __half sAhi[128 * APITCH];
    __shared__ __half sAlo[128 * APITCH];
    __shared__ __half sB[48 * APITCH];

    int t = threadIdx.x;
    int lane = t & 31;
    int wid = t >> 5;
    int m0 = blockIdx.x * 128;
    int wm = (wid & 3) * 32;
    int wn = (wid >> 2) * 24;

    float acc[2][3][4];
    #pragma unroll
    for (int i = 0; i < 2; i++)
        #pragma unroll
        for (int j = 0; j < 3; j++)
            #pragma unroll
            for (int q = 0; q < 4; q++) acc[i][j][q] = 0.f;

    int lrow = t >> 1;
    int lq   = (t & 1) << 3;
    int grow = m0 + lrow;

    uint32_t aHi = sptr(sAhi), aLo = sptr(sAlo), bB = sptr(sB);
    int a_r = (lane & 15);
    int a_c = (lane >> 4) << 3;
    int b_r = (lane & 7) + ((lane >> 4) << 3);
    int b_c = ((lane >> 3) & 1) << 3;
    int b2_r = lane & 7;
    int b2_c = ((lane >> 3) & 1) << 3;

    float4 pA0, pA1;
    uint4 pB;

    auto ldA = [&](int kc) {
        const float* Ab = (kc < 16) ? (g_h + kc * 16) : (g_hn2 + (kc - 16) * 16);
        if (grow < N_DST2) {
            const float* p = Ab + (size_t)grow * H_F + lq;
            pA0 = *(const float4*)p;
            pA1 = *(const float4*)(p + 4);
        } else {
            pA0 = make_float4(0.f, 0.f, 0.f, 0.f);
            pA1 = make_float4(0.f, 0.f, 0.f, 0.f);
        }
    };
    auto ldB = [&](int kc) {
        if (t < 96) {
            int row = t >> 1;
            int half = (t & 1) << 3;
            pB = *(const uint4*)(g_W2 + (size_t)row * 512 + kc * 16 + half);
        }
    };
    auto sts = [&]() {
        uint4 hi, lo;
        split8h(pA0, pA1, hi, lo);
        *(uint4*)&sAhi[lrow * APITCH + lq] = hi;
        *(uint4*)&sAlo[lrow * APITCH + lq] = lo;
        if (t < 96) {
            int row = t >> 1;
            int half = (t & 1) << 3;
            *(uint4*)&sB[row * APITCH + half] = pB;
        }
    };
    auto fused = [&]() {
        uint32_t ah[2][4], al[2][4];
        #pragma unroll
        for (int mf = 0; mf < 2; mf++) {
            uint32_t ao = ((wm + mf * 16 + a_r) * APITCH + a_c) * 2;
            ldm_x4(ah[mf], aHi + ao);
            ldm_x4(al[mf], aLo + ao);
        }
        uint32_t b4[4], bx2[2];
        ldm_x4(b4, bB + ((wn + b_r) * APITCH + b_c) * 2);
        ldm_x2(bx2, bB + ((wn + 16 + b2_r) * APITCH + b2_c) * 2);
        #pragma unroll
        for (int mf = 0; mf < 2; mf++) {
            mma16816(acc[mf][0], ah[mf], b4[0], b4[1]);
            mma16816(acc[mf][1], ah[mf], b4[2], b4[3]);
            mma16816(acc[mf][2], ah[mf], bx2[0], bx2[1]);
            mma16816(acc[mf][0], al[mf], b4[0], b4[1]);
            mma16816(acc[mf][1], al[mf], b4[2], b4[3]);
            mma16816(acc[mf][2], al[mf], bx2[0], bx2[1]);
        }
    };

    ldA(0);
    ldB(0);
    for (int kc = 0; kc < 32; kc++) {
        sts();
        __syncthreads();
        if (kc < 31) { ldA(kc + 1); ldB(kc + 1); }
        fused();
        __syncthreads();
    }

    #pragma unroll
    for (int mf = 0; mf < 2; mf++) {
        int gr0 = m0 + wm + mf * 16 + (lane >> 2);
        int gr1 = gr0 + 8;
        #pragma unroll
        for (int nf = 0; nf < 3; nf++) {
            int gn = wn + nf * 8 + ((lane & 3) << 1);
            float* d = acc[mf][nf];
            if (gn < N_CLS) {
                float bx = b2[gn];
                if (gr0 < N_DST2) out[(size_t)gr0 * N_CLS + gn] = d[0] + bx;
                if (gr1 < N_DST2) out[(size_t)gr1 * N_CLS + gn] = d[2] + bx;
            }
            if (gn + 1 < N_CLS) {
                float by = b2[gn + 1];
                if (gr0 < N_DST2) out[(size_t)gr0 * N_CLS + gn + 1] = d[1] + by;
                if (gr1 < N_DST2) out[(size_t)gr1 * N_CLS + gn + 1] = d[3] + by;
            }
        }
    }

    // rezero counts for the next graph replay (grid-stride)
    int stride = gridDim.x * blockDim.x;
    for (int i = blockIdx.x * blockDim.x + t; i < N_DST1; i += stride) g_cnt1[i] = 0;
    for (int i = blockIdx.x * blockDim.x + t; i < N_DST2; i += stride) g_cnt2[i] = 0;
}

// ---------------- launch ----------------
extern "C" void kernel_launch(void* const* d_in, const int* in_sizes, int n_in,
                              void* d_out, int out_size) {
    const float* x   = (const float*)d_in[0];
    const float* Ws1 = (const float*)d_in[1];
    const float* Wn1 = (const float*)d_in[2];
    const float* b1  = (const float*)d_in[3];
    const float* Ws2 = (const float*)d_in[4];
    const float* Wn2 = (const float*)d_in[5];
    const float* b2  = (const float*)d_in[6];
    const int* src1  = (const int*)d_in[7];
    const int* dst1  = (const int*)d_in[8];
    const int* src2  = (const int*)d_in[9];
    const int* dst2  = (const int*)d_in[10];
    float* out = (float*)d_out;

    k_count_split<<<(E1 + 255) / 256, 256>>>(dst1, dst2, Ws1, Wn1, Ws2, Wn2);  // 0
    k_scanA<<<NB1 + NB2, 1024>>>();                                            // 1
    k_scanC<<<NB1 + NB2, 1024>>>();                                            // 2 (scanB folded in)
    k_fill<<<(E1 + 255) / 256, 256>>>(src1, dst1, src2, dst2);                 // 3
    k_agg1<<<(N_DST1 * 32 + 255) / 256, 256>>>((const float4*)x);              // 4
    dim3 g1(2, (N_DST1 + 127) / 128);
    k_gemm1<<<g1, 256>>>(x, b1);                                               // 5
    k_agg2<<<(N_DST2 * 32 + 255) / 256, 256>>>();                              // 6
    k_gemm2<<<(N_DST2 + 127) / 128, 256>>>(b2, out);                           // 7
}